// round 1
// baseline (speedup 1.0000x reference)
#include <cuda_runtime.h>
#include <cuda_bf16.h>
#include <math.h>

// Problem constants (fixed by the reference)
#define NN 20000
#define DD 256
#define EE 640000
#define GG 64
#define ET (EE + NN)   // edges + self loops

// ---------------- device scratch (no allocations allowed) ----------------
__device__ float g_h[NN * DD];     // GEMM output / layer input
__device__ float g_t[NN * DD];     // aggregate output
__device__ float g_as[NN];         // alpha_src per node
__device__ float g_ad[NN];         // alpha_dst per node
__device__ int   g_cnt[NN];        // histogram
__device__ int   g_cur[NN];        // scatter cursor
__device__ int   g_rp[NN + 1];     // CSR row pointers (by dst)
__device__ int   g_srcidx[ET];     // src node ids grouped by dst
__device__ float g_sums[GG * DD];  // pooled sums

// ---------------- helpers ----------------
__device__ __forceinline__ float leaky(float x, float s) { return x > 0.f ? x : s * x; }

__device__ int lowerb(const int* __restrict__ a, int n, int key) {
    int lo = 0, hi = n;
    while (lo < hi) { int mid = (lo + hi) >> 1; if (a[mid] < key) lo = mid + 1; else hi = mid; }
    return lo;
}

// ---------------- zero kernels ----------------
__global__ void zero_f(float* p, int n) {
    int i = blockIdx.x * blockDim.x + threadIdx.x;
    if (i < n) p[i] = 0.f;
}
__global__ void zero_i(int* p, int n) {
    int i = blockIdx.x * blockDim.x + threadIdx.x;
    if (i < n) p[i] = 0;
}

// ---------------- CSR build ----------------
__global__ void hist_kernel(const int* __restrict__ dst, int e) {
    int i = blockIdx.x * blockDim.x + threadIdx.x;
    if (i < e) atomicAdd(&g_cnt[dst[i]], 1);
}

// single block exclusive scan of (g_cnt[i] + 1)  (+1 = self loop)
__global__ void scan_kernel(int n) {
    __shared__ int sm[1024];
    __shared__ int carry;
    int tid = threadIdx.x;
    if (tid == 0) { carry = 0; g_rp[0] = 0; }
    __syncthreads();
    for (int base = 0; base < n; base += 1024) {
        int i = base + tid;
        int v = (i < n) ? (g_cnt[i] + 1) : 0;
        sm[tid] = v;
        __syncthreads();
        for (int off = 1; off < 1024; off <<= 1) {
            int t = (tid >= off) ? sm[tid - off] : 0;
            __syncthreads();
            sm[tid] += t;
            __syncthreads();
        }
        int c = carry;
        if (i < n) g_rp[i + 1] = c + sm[tid];
        __syncthreads();
        if (tid == 0) carry = c + sm[1023];
        __syncthreads();
    }
}

__global__ void scatter_kernel(const int* __restrict__ src, const int* __restrict__ dst, int e, int n) {
    int i = blockIdx.x * blockDim.x + threadIdx.x;
    if (i < e) {
        int d = dst[i];
        int p = g_rp[d] + atomicAdd(&g_cur[d], 1);
        g_srcidx[p] = src[i];
    } else if (i < e + n) {
        int v = i - e;
        int p = g_rp[v] + atomicAdd(&g_cur[v], 1);
        g_srcidx[p] = v;
    }
}

// ---------------- SGEMM with fused alpha epilogue ----------------
// C[M,256] = A[M,256] @ B[256,256];  as[m] += C[m,:]·a_src, ad[m] += C[m,:]·a_dst
#define BM 128
#define BNb 128
#define BK 16
__global__ __launch_bounds__(256, 2)
void sgemm_alpha(const float* __restrict__ A, const float* __restrict__ B,
                 float* __restrict__ C,
                 const float* __restrict__ a_src, const float* __restrict__ a_dst,
                 float* __restrict__ asv, float* __restrict__ adv, int M) {
    __shared__ float As[BK][BM];
    __shared__ float Bs[BK][BNb];
    const int K = DD;
    int tid = threadIdx.x;
    int tx = tid & 15, ty = tid >> 4;
    int rowBase = blockIdx.y * BM;
    int colBase = blockIdx.x * BNb;
    float acc[8][8];
#pragma unroll
    for (int i = 0; i < 8; i++)
#pragma unroll
        for (int j = 0; j < 8; j++) acc[i][j] = 0.f;

    for (int k0 = 0; k0 < K; k0 += BK) {
#pragma unroll
        for (int i = 0; i < 2; i++) {
            int f = tid + i * 256;
            int r = f >> 2;
            int c4 = (f & 3) * 4;
            int gr = rowBase + r;
            float4 v = make_float4(0.f, 0.f, 0.f, 0.f);
            if (gr < M) v = *(const float4*)(A + (size_t)gr * K + k0 + c4);
            As[c4 + 0][r] = v.x; As[c4 + 1][r] = v.y;
            As[c4 + 2][r] = v.z; As[c4 + 3][r] = v.w;
        }
#pragma unroll
        for (int i = 0; i < 2; i++) {
            int f = tid + i * 256;
            int r = f >> 5;
            int c4 = (f & 31) * 4;
            float4 v = *(const float4*)(B + (size_t)(k0 + r) * DD + colBase + c4);
            *(float4*)&Bs[r][c4] = v;
        }
        __syncthreads();
#pragma unroll
        for (int k = 0; k < BK; k++) {
            float ar[8], br[8];
#pragma unroll
            for (int i = 0; i < 8; i++) ar[i] = As[k][ty * 8 + i];
#pragma unroll
            for (int j = 0; j < 8; j++) br[j] = Bs[k][tx * 8 + j];
#pragma unroll
            for (int i = 0; i < 8; i++)
#pragma unroll
                for (int j = 0; j < 8; j++) acc[i][j] += ar[i] * br[j];
        }
        __syncthreads();
    }

    // epilogue: store C + alpha partial dots
    float asr[8], adr[8];
#pragma unroll
    for (int j = 0; j < 8; j++) {
        int gc = colBase + tx * 8 + j;
        asr[j] = __ldg(a_src + gc);
        adr[j] = __ldg(a_dst + gc);
    }
#pragma unroll
    for (int i = 0; i < 8; i++) {
        int gr = rowBase + ty * 8 + i;
        if (gr >= M) continue;
        float ps = 0.f, pd = 0.f;
#pragma unroll
        for (int j = 0; j < 8; j++) {
            ps += acc[i][j] * asr[j];
            pd += acc[i][j] * adr[j];
        }
        float* cp = C + (size_t)gr * DD + colBase + tx * 8;
        *(float4*)cp       = make_float4(acc[i][0], acc[i][1], acc[i][2], acc[i][3]);
        *(float4*)(cp + 4) = make_float4(acc[i][4], acc[i][5], acc[i][6], acc[i][7]);
        atomicAdd(asv + gr, ps);
        atomicAdd(adv + gr, pd);
    }
}

// ---------------- fused GAT aggregation (softmax + weighted sum + bias + leaky) ----------------
// one warp per destination node
__global__ __launch_bounds__(256)
void gat_aggregate(const float* __restrict__ h,
                   const float* __restrict__ asv, const float* __restrict__ adv,
                   const float* __restrict__ bias, float* __restrict__ out, int n) {
    int warp = (blockIdx.x * blockDim.x + threadIdx.x) >> 5;
    int lane = threadIdx.x & 31;
    if (warp >= n) return;
    int v = warp;
    int beg = g_rp[v], end = g_rp[v + 1];
    float adval = adv[v];

    // pass 1: max of leaky(as[src] + ad[v])
    float m = -1e30f;
    for (int j = beg + lane; j < end; j += 32) {
        float e = leaky(__ldg(asv + g_srcidx[j]) + adval, 0.2f);
        m = fmaxf(m, e);
    }
#pragma unroll
    for (int off = 16; off; off >>= 1) m = fmaxf(m, __shfl_xor_sync(0xffffffffu, m, off));

    // pass 2: accumulate unnormalized exp * h[src], and the softmax denominator
    float acc[8];
#pragma unroll
    for (int i = 0; i < 8; i++) acc[i] = 0.f;
    float ssum = 0.f;

    for (int j0 = beg; j0 < end; j0 += 32) {
        int j = j0 + lane;
        float w = 0.f; int s = 0;
        if (j < end) {
            s = g_srcidx[j];
            float e = leaky(__ldg(asv + s) + adval, 0.2f);
            w = __expf(e - m);
        }
        ssum += w;
        int cnt = min(32, end - j0);
        for (int k = 0; k < cnt; k++) {
            float wk = __shfl_sync(0xffffffffu, w, k);
            int   sk = __shfl_sync(0xffffffffu, s, k);
            const float4* hp = (const float4*)(h + (size_t)sk * DD + lane * 8);
            float4 v0 = __ldg(hp);
            float4 v1 = __ldg(hp + 1);
            acc[0] += wk * v0.x; acc[1] += wk * v0.y;
            acc[2] += wk * v0.z; acc[3] += wk * v0.w;
            acc[4] += wk * v1.x; acc[5] += wk * v1.y;
            acc[6] += wk * v1.z; acc[7] += wk * v1.w;
        }
    }
#pragma unroll
    for (int off = 16; off; off >>= 1) ssum += __shfl_xor_sync(0xffffffffu, ssum, off);
    float inv = 1.0f / ssum;   // self loop guarantees ssum > 0

    float* op = out + (size_t)v * DD + lane * 8;
    float4 o0, o1;
    o0.x = leaky(acc[0] * inv + __ldg(bias + lane * 8 + 0), 0.01f);
    o0.y = leaky(acc[1] * inv + __ldg(bias + lane * 8 + 1), 0.01f);
    o0.z = leaky(acc[2] * inv + __ldg(bias + lane * 8 + 2), 0.01f);
    o0.w = leaky(acc[3] * inv + __ldg(bias + lane * 8 + 3), 0.01f);
    o1.x = leaky(acc[4] * inv + __ldg(bias + lane * 8 + 4), 0.01f);
    o1.y = leaky(acc[5] * inv + __ldg(bias + lane * 8 + 5), 0.01f);
    o1.z = leaky(acc[6] * inv + __ldg(bias + lane * 8 + 6), 0.01f);
    o1.w = leaky(acc[7] * inv + __ldg(bias + lane * 8 + 7), 0.01f);
    *(float4*)op       = o0;
    *(float4*)(op + 4) = o1;
}

// ---------------- pooling ----------------
#define NSPLIT 16
__global__ void pool_kernel(const float* __restrict__ t, const int* __restrict__ batch, int n) {
    int g = blockIdx.x;
    int split = blockIdx.y;
    int lo = lowerb(batch, n, g);
    int hi = lowerb(batch, n, g + 1);
    int cnt = hi - lo;
    if (cnt <= 0) return;
    int per = (cnt + NSPLIT - 1) / NSPLIT;
    int s0 = lo + split * per;
    int s1 = min(hi, s0 + per);
    if (s0 >= s1) return;
    int d = threadIdx.x;
    float a = 0.f;
    for (int nn = s0; nn < s1; nn++) a += t[(size_t)nn * DD + d];
    atomicAdd(&g_sums[g * DD + d], a);
}

// ---------------- finalize: mean + BN + linear ----------------
__global__ void finalize_kernel(const int* __restrict__ batch,
                                const float* __restrict__ gamma, const float* __restrict__ beta,
                                const float* __restrict__ mean, const float* __restrict__ var,
                                const float* __restrict__ Wl, const float* __restrict__ bl,
                                float* __restrict__ out, int n) {
    int g = blockIdx.x;
    int d = threadIdx.x;
    __shared__ float p[DD];
    __shared__ int scnt;
    if (d == 0) scnt = lowerb(batch, n, g + 1) - lowerb(batch, n, g);
    __syncthreads();
    float c = fmaxf((float)scnt, 1.0f);
    float vv = g_sums[g * DD + d] / c;
    vv = (vv - mean[d]) * rsqrtf(var[d] + 1e-5f) * gamma[d] + beta[d];
    p[d] = vv;
    __syncthreads();
    float o = bl[d];
    const float* wr = Wl + (size_t)d * DD;
    for (int k = 0; k < DD; k++) o += p[k] * wr[k];
    out[(size_t)g * DD + d] = o;
}

// ---------------- launch ----------------
extern "C" void kernel_launch(void* const* d_in, const int* in_sizes, int n_in,
                              void* d_out, int out_size) {
    const float* x      = (const float*)d_in[0];
    const int*   ei     = (const int*)d_in[1];
    const int*   batch  = (const int*)d_in[2];
    const float* W1     = (const float*)d_in[3];
    const float* a1s    = (const float*)d_in[4];
    const float* a1d    = (const float*)d_in[5];
    const float* b1     = (const float*)d_in[6];
    const float* W2     = (const float*)d_in[7];
    const float* a2s    = (const float*)d_in[8];
    const float* a2d    = (const float*)d_in[9];
    const float* b2     = (const float*)d_in[10];
    const float* gam    = (const float*)d_in[11];
    const float* bet    = (const float*)d_in[12];
    const float* mu     = (const float*)d_in[13];
    const float* var    = (const float*)d_in[14];
    const float* Wl     = (const float*)d_in[15];
    const float* bl     = (const float*)d_in[16];
    float* out = (float*)d_out;

    const int n = in_sizes[2];         // 20000
    const int e = in_sizes[1] / 2;     // 640000
    const int* srcp = ei;
    const int* dstp = ei + e;

    float* hptr;   cudaGetSymbolAddress((void**)&hptr, g_h);
    float* tptr;   cudaGetSymbolAddress((void**)&tptr, g_t);
    float* asp;    cudaGetSymbolAddress((void**)&asp, g_as);
    float* adp;    cudaGetSymbolAddress((void**)&adp, g_ad);
    int*   cntp;   cudaGetSymbolAddress((void**)&cntp, g_cnt);
    int*   curp;   cudaGetSymbolAddress((void**)&curp, g_cur);
    float* sumsp;  cudaGetSymbolAddress((void**)&sumsp, g_sums);

    const int T = 256;

    // zero scratch
    zero_i<<<(n + T - 1) / T, T>>>(cntp, n);
    zero_i<<<(n + T - 1) / T, T>>>(curp, n);
    zero_f<<<(n + T - 1) / T, T>>>(asp, n);
    zero_f<<<(n + T - 1) / T, T>>>(adp, n);
    zero_f<<<(GG * DD + T - 1) / T, T>>>(sumsp, GG * DD);

    // CSR build (once; reused by both layers)
    hist_kernel<<<(e + T - 1) / T, T>>>(dstp, e);
    scan_kernel<<<1, 1024>>>(n);
    scatter_kernel<<<(e + n + T - 1) / T, T>>>(srcp, dstp, e, n);

    dim3 ggrid(DD / BNb, (n + BM - 1) / BM);
    int aggBlocks = (n * 32 + T - 1) / T;

    // layer 1
    sgemm_alpha<<<ggrid, 256>>>(x, W1, hptr, a1s, a1d, asp, adp, n);
    gat_aggregate<<<aggBlocks, T>>>(hptr, asp, adp, b1, tptr, n);

    // layer 2
    zero_f<<<(n + T - 1) / T, T>>>(asp, n);
    zero_f<<<(n + T - 1) / T, T>>>(adp, n);
    sgemm_alpha<<<ggrid, 256>>>(tptr, W2, hptr, a2s, a2d, asp, adp, n);
    gat_aggregate<<<aggBlocks, T>>>(hptr, asp, adp, b2, tptr, n);

    // pool + finalize (BN folded onto pooled means — pooling is linear)
    dim3 pgrid(GG, NSPLIT);
    pool_kernel<<<pgrid, DD>>>(tptr, batch, n);
    finalize_kernel<<<GG, DD>>>(batch, gam, bet, mu, var, Wl, bl, out, n);
}

// round 2
// speedup vs baseline: 1.2238x; 1.2238x over previous
#include <cuda_runtime.h>
#include <cuda_fp16.h>
#include <math.h>

// Problem constants (fixed by the reference)
#define NN 20000
#define DD 256
#define EE 640000
#define GG 64
#define ET (EE + NN)   // edges + self loops

// ---------------- device scratch (no allocations allowed) ----------------
__device__ __half g_hh[NN * DD];      // GEMM output in fp16 (gather payload)
__device__ float  g_t[NN * DD];       // aggregate output (fp32)
__device__ float  g_as[2 * NN];       // alpha_src partials (per column block)
__device__ float  g_ad[2 * NN];       // alpha_dst partials
__device__ int    g_cnt[NN];          // histogram
__device__ int    g_cur[NN];          // scatter cursor
__device__ int    g_rp[NN + 1];       // CSR row pointers (by dst)
__device__ int    g_srcidx[ET];       // src node ids grouped by dst
__device__ float  g_sums[GG * DD];    // pooled sums

// ---------------- helpers ----------------
__device__ __forceinline__ float leaky(float x, float s) { return x > 0.f ? x : s * x; }

__device__ int lowerb(const int* __restrict__ a, int n, int key) {
    int lo = 0, hi = n;
    while (lo < hi) { int mid = (lo + hi) >> 1; if (a[mid] < key) lo = mid + 1; else hi = mid; }
    return lo;
}

// ---------------- init (zero cnt/cur/sums in one launch) ----------------
__global__ void init_kernel() {
    int i = blockIdx.x * blockDim.x + threadIdx.x;
    if (i < NN) { g_cnt[i] = 0; g_cur[i] = 0; }
    if (i < GG * DD) g_sums[i] = 0.f;
}

// ---------------- CSR build ----------------
__global__ void hist_kernel(const int* __restrict__ dst, int e) {
    int i = blockIdx.x * blockDim.x + threadIdx.x;
    int i4 = i * 4;
    if (i4 + 3 < e) {
        int4 d = *(const int4*)(dst + i4);
        atomicAdd(&g_cnt[d.x], 1);
        atomicAdd(&g_cnt[d.y], 1);
        atomicAdd(&g_cnt[d.z], 1);
        atomicAdd(&g_cnt[d.w], 1);
    } else {
        for (int j = i4; j < e; j++) atomicAdd(&g_cnt[dst[j]], 1);
    }
}

// exclusive scan of (g_cnt[i] + 1), single block, thread-sequential chunks
__global__ void scan_kernel(int n) {
    __shared__ int part[1024];
    int tid = threadIdx.x;
    const int C = (n + 1023) >> 10;     // 20 for n=20000
    int s0 = tid * C;
    int s1 = min(n, s0 + C);
    int local[32];
    int sum = 0;
    for (int i = s0; i < s1; i++) { local[i - s0] = sum; sum += g_cnt[i] + 1; }
    part[tid] = sum;
    __syncthreads();
    for (int off = 1; off < 1024; off <<= 1) {
        int t = (tid >= off) ? part[tid - off] : 0;
        __syncthreads();
        part[tid] += t;
        __syncthreads();
    }
    int base = (tid > 0) ? part[tid - 1] : 0;
    for (int i = s0; i < s1; i++) g_rp[i] = base + local[i - s0];
    if (tid == 1023) g_rp[n] = part[1023];
}

__global__ void scatter_edges(const int* __restrict__ src, const int* __restrict__ dst, int e) {
    int i = blockIdx.x * blockDim.x + threadIdx.x;
    int i4 = i * 4;
    if (i4 + 3 < e) {
        int4 s = *(const int4*)(src + i4);
        int4 d = *(const int4*)(dst + i4);
        g_srcidx[g_rp[d.x] + atomicAdd(&g_cur[d.x], 1)] = s.x;
        g_srcidx[g_rp[d.y] + atomicAdd(&g_cur[d.y], 1)] = s.y;
        g_srcidx[g_rp[d.z] + atomicAdd(&g_cur[d.z], 1)] = s.z;
        g_srcidx[g_rp[d.w] + atomicAdd(&g_cur[d.w], 1)] = s.w;
    } else {
        for (int j = i4; j < e; j++) {
            int d = dst[j];
            g_srcidx[g_rp[d] + atomicAdd(&g_cur[d], 1)] = src[j];
        }
    }
}

__global__ void scatter_loops(int n) {
    int v = blockIdx.x * blockDim.x + threadIdx.x;
    if (v < n) g_srcidx[g_rp[v] + atomicAdd(&g_cur[v], 1)] = v;
}

// ---------------- double-buffered SGEMM, fp16 C store, fused alpha epilogue ----
// C_half[M,256] = A[M,256] @ B[256,256]
// as[cb][m] = sum over this column block of C[m,:]*a_src (shfl-reduced, no atomics)
#define BM 128
#define BNb 128
#define BK 16
__global__ __launch_bounds__(256, 2)
void sgemm_alpha(const float* __restrict__ A, const float* __restrict__ B,
                 __half* __restrict__ Ch,
                 const float* __restrict__ a_src, const float* __restrict__ a_dst,
                 float* __restrict__ asv, float* __restrict__ adv, int M) {
    __shared__ float As[2][BK][BM];
    __shared__ float Bs[2][BK][BNb];
    const int K = DD;
    int tid = threadIdx.x;
    int tx = tid & 15, ty = tid >> 4;
    int rowBase = blockIdx.y * BM;
    int colBase = blockIdx.x * BNb;

    // load index precompute: 512 float4 per operand tile, 2 per thread
    int fa0 = tid, fa1 = tid + 256;
    int arow0 = fa0 >> 2, ac0 = (fa0 & 3) * 4;
    int arow1 = fa1 >> 2, ac1 = (fa1 & 3) * 4;
    int brow0 = fa0 >> 5, bc0 = (fa0 & 31) * 4;
    int brow1 = fa1 >> 5, bc1 = (fa1 & 31) * 4;

    float acc[8][8];
#pragma unroll
    for (int i = 0; i < 8; i++)
#pragma unroll
        for (int j = 0; j < 8; j++) acc[i][j] = 0.f;

    float4 ra0, ra1, rb0, rb1;
    // prologue: tile 0 -> regs -> smem[0]
    {
        int gr0 = rowBase + arow0, gr1 = rowBase + arow1;
        ra0 = (gr0 < M) ? *(const float4*)(A + (size_t)gr0 * K + ac0) : make_float4(0, 0, 0, 0);
        ra1 = (gr1 < M) ? *(const float4*)(A + (size_t)gr1 * K + ac1) : make_float4(0, 0, 0, 0);
        rb0 = *(const float4*)(B + (size_t)brow0 * DD + colBase + bc0);
        rb1 = *(const float4*)(B + (size_t)brow1 * DD + colBase + bc1);
        As[0][ac0 + 0][arow0] = ra0.x; As[0][ac0 + 1][arow0] = ra0.y;
        As[0][ac0 + 2][arow0] = ra0.z; As[0][ac0 + 3][arow0] = ra0.w;
        As[0][ac1 + 0][arow1] = ra1.x; As[0][ac1 + 1][arow1] = ra1.y;
        As[0][ac1 + 2][arow1] = ra1.z; As[0][ac1 + 3][arow1] = ra1.w;
        *(float4*)&Bs[0][brow0][bc0] = rb0;
        *(float4*)&Bs[0][brow1][bc1] = rb1;
    }
    __syncthreads();

    int p = 0;
    const int NT = K / BK;  // 16
    for (int it = 0; it < NT; it++) {
        if (it < NT - 1) {
            int k0 = (it + 1) * BK;
            int gr0 = rowBase + arow0, gr1 = rowBase + arow1;
            ra0 = (gr0 < M) ? *(const float4*)(A + (size_t)gr0 * K + k0 + ac0) : make_float4(0, 0, 0, 0);
            ra1 = (gr1 < M) ? *(const float4*)(A + (size_t)gr1 * K + k0 + ac1) : make_float4(0, 0, 0, 0);
            rb0 = *(const float4*)(B + (size_t)(k0 + brow0) * DD + colBase + bc0);
            rb1 = *(const float4*)(B + (size_t)(k0 + brow1) * DD + colBase + bc1);
        }
#pragma unroll
        for (int k = 0; k < BK; k++) {
            float ar[8], br[8];
#pragma unroll
            for (int i = 0; i < 8; i++) ar[i] = As[p][k][ty * 8 + i];
#pragma unroll
            for (int j = 0; j < 8; j++) br[j] = Bs[p][k][tx * 8 + j];
#pragma unroll
            for (int i = 0; i < 8; i++)
#pragma unroll
                for (int j = 0; j < 8; j++) acc[i][j] += ar[i] * br[j];
        }
        if (it < NT - 1) {
            int q = p ^ 1;
            As[q][ac0 + 0][arow0] = ra0.x; As[q][ac0 + 1][arow0] = ra0.y;
            As[q][ac0 + 2][arow0] = ra0.z; As[q][ac0 + 3][arow0] = ra0.w;
            As[q][ac1 + 0][arow1] = ra1.x; As[q][ac1 + 1][arow1] = ra1.y;
            As[q][ac1 + 2][arow1] = ra1.z; As[q][ac1 + 3][arow1] = ra1.w;
            *(float4*)&Bs[q][brow0][bc0] = rb0;
            *(float4*)&Bs[q][brow1][bc1] = rb1;
            __syncthreads();
            p = q;
        }
    }

    // epilogue: half store + alpha partial dots, shfl-reduced across tx (16 lanes)
    float asr[8], adr[8];
#pragma unroll
    for (int j = 0; j < 8; j++) {
        int gc = colBase + tx * 8 + j;
        asr[j] = __ldg(a_src + gc);
        adr[j] = __ldg(a_dst + gc);
    }
    float* asout = asv + blockIdx.x * NN;
    float* adout = adv + blockIdx.x * NN;
#pragma unroll
    for (int i = 0; i < 8; i++) {
        int gr = rowBase + ty * 8 + i;
        float ps = 0.f, pd = 0.f;
#pragma unroll
        for (int j = 0; j < 8; j++) {
            ps += acc[i][j] * asr[j];
            pd += acc[i][j] * adr[j];
        }
        // reduce across tx within the 16-lane group
#pragma unroll
        for (int off = 8; off; off >>= 1) {
            ps += __shfl_xor_sync(0xffffffffu, ps, off);
            pd += __shfl_xor_sync(0xffffffffu, pd, off);
        }
        if (gr < M) {
            __half2 h01 = __floats2half2_rn(acc[i][0], acc[i][1]);
            __half2 h23 = __floats2half2_rn(acc[i][2], acc[i][3]);
            __half2 h45 = __floats2half2_rn(acc[i][4], acc[i][5]);
            __half2 h67 = __floats2half2_rn(acc[i][6], acc[i][7]);
            uint4 pk;
            pk.x = *(unsigned*)&h01; pk.y = *(unsigned*)&h23;
            pk.z = *(unsigned*)&h45; pk.w = *(unsigned*)&h67;
            *(uint4*)(Ch + (size_t)gr * DD + colBase + tx * 8) = pk;
            if (tx == 0) { asout[gr] = ps; adout[gr] = pd; }
        }
    }
}

// ---------------- fused GAT aggregation (softmax + weighted sum + bias + leaky) ----
// one warp per destination node; h rows are fp16
__global__ __launch_bounds__(256)
void gat_aggregate(const __half* __restrict__ h,
                   const float* __restrict__ asv, const float* __restrict__ adv,
                   const float* __restrict__ bias, float* __restrict__ out, int n) {
    int warp = (blockIdx.x * blockDim.x + threadIdx.x) >> 5;
    int lane = threadIdx.x & 31;
    if (warp >= n) return;
    int v = warp;
    int beg = g_rp[v], end = g_rp[v + 1];
    float adval = adv[v] + adv[NN + v];

    float acc[8];
#pragma unroll
    for (int i = 0; i < 8; i++) acc[i] = 0.f;
    float ssum = 0.f;

    for (int j0 = beg; j0 < end; j0 += 32) {
        int j = j0 + lane;
        float w = 0.f; int s = 0;
        if (j < end) {
            s = g_srcidx[j];
            float e = leaky(asv[s] + asv[NN + s] + adval, 0.2f);
            w = __expf(e);   // logits bounded; no max-shift needed
        }
        ssum += w;
        int cnt = min(32, end - j0);
        int k = 0;
        for (; k + 2 <= cnt; k += 2) {
            float wk0 = __shfl_sync(0xffffffffu, w, k);
            float wk1 = __shfl_sync(0xffffffffu, w, k + 1);
            int sk0 = __shfl_sync(0xffffffffu, s, k);
            int sk1 = __shfl_sync(0xffffffffu, s, k + 1);
            uint4 ha = __ldg((const uint4*)(h + (size_t)sk0 * DD) + lane);
            uint4 hb = __ldg((const uint4*)(h + (size_t)sk1 * DD) + lane);
            const __half2* pa = (const __half2*)&ha;
            const __half2* pb = (const __half2*)&hb;
#pragma unroll
            for (int q = 0; q < 4; q++) {
                float2 fa = __half22float2(pa[q]);
                float2 fb = __half22float2(pb[q]);
                acc[2 * q + 0] += wk0 * fa.x + wk1 * fb.x;
                acc[2 * q + 1] += wk0 * fa.y + wk1 * fb.y;
            }
        }
        if (k < cnt) {
            float wk = __shfl_sync(0xffffffffu, w, k);
            int sk = __shfl_sync(0xffffffffu, s, k);
            uint4 ha = __ldg((const uint4*)(h + (size_t)sk * DD) + lane);
            const __half2* pa = (const __half2*)&ha;
#pragma unroll
            for (int q = 0; q < 4; q++) {
                float2 fa = __half22float2(pa[q]);
                acc[2 * q + 0] += wk * fa.x;
                acc[2 * q + 1] += wk * fa.y;
            }
        }
    }
#pragma unroll
    for (int off = 16; off; off >>= 1) ssum += __shfl_xor_sync(0xffffffffu, ssum, off);
    float inv = 1.0f / ssum;   // self loop guarantees ssum > 0

    float* op = out + (size_t)v * DD + lane * 8;
    float4 o0, o1;
    o0.x = leaky(acc[0] * inv + __ldg(bias + lane * 8 + 0), 0.01f);
    o0.y = leaky(acc[1] * inv + __ldg(bias + lane * 8 + 1), 0.01f);
    o0.z = leaky(acc[2] * inv + __ldg(bias + lane * 8 + 2), 0.01f);
    o0.w = leaky(acc[3] * inv + __ldg(bias + lane * 8 + 3), 0.01f);
    o1.x = leaky(acc[4] * inv + __ldg(bias + lane * 8 + 4), 0.01f);
    o1.y = leaky(acc[5] * inv + __ldg(bias + lane * 8 + 5), 0.01f);
    o1.z = leaky(acc[6] * inv + __ldg(bias + lane * 8 + 6), 0.01f);
    o1.w = leaky(acc[7] * inv + __ldg(bias + lane * 8 + 7), 0.01f);
    *(float4*)op       = o0;
    *(float4*)(op + 4) = o1;
}

// ---------------- pooling ----------------
#define NSPLIT 16
__global__ void pool_kernel(const float* __restrict__ t, const int* __restrict__ batch, int n) {
    int g = blockIdx.x;
    int split = blockIdx.y;
    int lo = lowerb(batch, n, g);
    int hi = lowerb(batch, n, g + 1);
    int cnt = hi - lo;
    if (cnt <= 0) return;
    int per = (cnt + NSPLIT - 1) / NSPLIT;
    int s0 = lo + split * per;
    int s1 = min(hi, s0 + per);
    if (s0 >= s1) return;
    int d = threadIdx.x;
    float a = 0.f;
    for (int nn = s0; nn < s1; nn++) a += t[(size_t)nn * DD + d];
    atomicAdd(&g_sums[g * DD + d], a);
}

// ---------------- finalize: mean + BN + linear ----------------
__global__ void finalize_kernel(const int* __restrict__ batch,
                                const float* __restrict__ gamma, const float* __restrict__ beta,
                                const float* __restrict__ mean, const float* __restrict__ var,
                                const float* __restrict__ Wl, const float* __restrict__ bl,
                                float* __restrict__ out, int n) {
    int g = blockIdx.x;
    int d = threadIdx.x;
    __shared__ float p[DD];
    __shared__ int scnt;
    if (d == 0) scnt = lowerb(batch, n, g + 1) - lowerb(batch, n, g);
    __syncthreads();
    float c = fmaxf((float)scnt, 1.0f);
    float vv = g_sums[g * DD + d] / c;
    vv = (vv - mean[d]) * rsqrtf(var[d] + 1e-5f) * gamma[d] + beta[d];
    p[d] = vv;
    __syncthreads();
    float o = bl[d];
    const float* wr = Wl + (size_t)d * DD;
    for (int k = 0; k < DD; k++) o += p[k] * wr[k];
    out[(size_t)g * DD + d] = o;
}

// ---------------- launch ----------------
extern "C" void kernel_launch(void* const* d_in, const int* in_sizes, int n_in,
                              void* d_out, int out_size) {
    const float* x      = (const float*)d_in[0];
    const int*   ei     = (const int*)d_in[1];
    const int*   batch  = (const int*)d_in[2];
    const float* W1     = (const float*)d_in[3];
    const float* a1s    = (const float*)d_in[4];
    const float* a1d    = (const float*)d_in[5];
    const float* b1     = (const float*)d_in[6];
    const float* W2     = (const float*)d_in[7];
    const float* a2s    = (const float*)d_in[8];
    const float* a2d    = (const float*)d_in[9];
    const float* b2     = (const float*)d_in[10];
    const float* gam    = (const float*)d_in[11];
    const float* bet    = (const float*)d_in[12];
    const float* mu     = (const float*)d_in[13];
    const float* var    = (const float*)d_in[14];
    const float* Wl     = (const float*)d_in[15];
    const float* bl     = (const float*)d_in[16];
    float* out = (float*)d_out;

    const int n = in_sizes[2];         // 20000
    const int e = in_sizes[1] / 2;     // 640000
    const int* srcp = ei;
    const int* dstp = ei + e;

    __half* hhp;  cudaGetSymbolAddress((void**)&hhp, g_hh);
    float* tptr;  cudaGetSymbolAddress((void**)&tptr, g_t);
    float* asp;   cudaGetSymbolAddress((void**)&asp, g_as);
    float* adp;   cudaGetSymbolAddress((void**)&adp, g_ad);

    const int T = 256;

    init_kernel<<<(NN + T - 1) / T, T>>>();

    // CSR build (once; reused by both layers)
    hist_kernel<<<((e + 3) / 4 + T - 1) / T, T>>>(dstp, e);
    scan_kernel<<<1, 1024>>>(n);
    scatter_edges<<<((e + 3) / 4 + T - 1) / T, T>>>(srcp, dstp, e);
    scatter_loops<<<(n + T - 1) / T, T>>>(n);

    dim3 ggrid(DD / BNb, (n + BM - 1) / BM);
    int aggBlocks = (n * 32 + T - 1) / T;

    // layer 1
    sgemm_alpha<<<ggrid, 256>>>(x, W1, hhp, a1s, a1d, asp, adp, n);
    gat_aggregate<<<aggBlocks, T>>>(hhp, asp, adp, b1, tptr, n);

    // layer 2 (alpha buffers fully overwritten by GEMM2 — no zeroing needed)
    sgemm_alpha<<<ggrid, 256>>>(tptr, W2, hhp, a2s, a2d, asp, adp, n);
    gat_aggregate<<<aggBlocks, T>>>(hhp, asp, adp, b2, tptr, n);

    // pool + finalize (BN folded onto pooled means — pooling is linear)
    dim3 pgrid(GG, NSPLIT);
    pool_kernel<<<pgrid, DD>>>(tptr, batch, n);
    finalize_kernel<<<GG, DD>>>(batch, gam, bet, mu, var, Wl, bl, out, n);
}

// round 4
// speedup vs baseline: 1.9926x; 1.6282x over previous
#include <cuda_runtime.h>
#include <cuda_fp16.h>
#include <cstdint>
#include <math.h>

// Problem constants (fixed by the reference)
#define NN 20000
#define DD 256
#define EE 640000
#define GG 64
#define ET (EE + NN)   // edges + self loops

// ---------------- device scratch (no allocations allowed) ----------------
__device__ __half g_hh[NN * DD];      // GEMM output in fp16 (gather payload)
__device__ float  g_t[NN * DD];       // aggregate output (fp32)
__device__ float  g_as[2 * NN];       // alpha_src partials (per column block)
__device__ float  g_ad[2 * NN];       // alpha_dst partials
__device__ int    g_cnt[NN];          // histogram
__device__ int    g_cur[NN];          // scatter cursor
__device__ int    g_rp[NN + 1];       // CSR row pointers (by dst)
__device__ int    g_srcidx[ET];       // src node ids grouped by dst
__device__ float  g_sums[GG * DD];    // pooled sums

// ---------------- helpers ----------------
__device__ __forceinline__ float leaky(float x, float s) { return x > 0.f ? x : s * x; }

__device__ int lowerb(const int* __restrict__ a, int n, int key) {
    int lo = 0, hi = n;
    while (lo < hi) { int mid = (lo + hi) >> 1; if (a[mid] < key) lo = mid + 1; else hi = mid; }
    return lo;
}

// ---------------- init (zero cnt/cur/sums in one launch) ----------------
__global__ void init_kernel() {
    int i = blockIdx.x * blockDim.x + threadIdx.x;
    if (i < NN) { g_cnt[i] = 0; g_cur[i] = 0; }
    if (i < GG * DD) g_sums[i] = 0.f;
}

// ---------------- CSR build ----------------
__global__ void hist_kernel(const int* __restrict__ dst, int e) {
    int i = blockIdx.x * blockDim.x + threadIdx.x;
    int i4 = i * 4;
    if (i4 + 3 < e) {
        int4 d = *(const int4*)(dst + i4);
        atomicAdd(&g_cnt[d.x], 1);
        atomicAdd(&g_cnt[d.y], 1);
        atomicAdd(&g_cnt[d.z], 1);
        atomicAdd(&g_cnt[d.w], 1);
    } else {
        for (int j = i4; j < e; j++) atomicAdd(&g_cnt[dst[j]], 1);
    }
}

// exclusive scan of (g_cnt[i] + 1), single block, thread-sequential chunks
__global__ void scan_kernel(int n) {
    __shared__ int part[1024];
    int tid = threadIdx.x;
    const int C = (n + 1023) >> 10;     // 20 for n=20000
    int s0 = tid * C;
    int s1 = min(n, s0 + C);
    int local[32];
    int sum = 0;
    for (int i = s0; i < s1; i++) { local[i - s0] = sum; sum += g_cnt[i] + 1; }
    part[tid] = sum;
    __syncthreads();
    for (int off = 1; off < 1024; off <<= 1) {
        int t = (tid >= off) ? part[tid - off] : 0;
        __syncthreads();
        part[tid] += t;
        __syncthreads();
    }
    int base = (tid > 0) ? part[tid - 1] : 0;
    for (int i = s0; i < s1; i++) g_rp[i] = base + local[i - s0];
    if (tid == 1023) g_rp[n] = part[1023];
}

__global__ void scatter_edges(const int* __restrict__ src, const int* __restrict__ dst, int e) {
    int i = blockIdx.x * blockDim.x + threadIdx.x;
    int i4 = i * 4;
    if (i4 + 3 < e) {
        int4 s = *(const int4*)(src + i4);
        int4 d = *(const int4*)(dst + i4);
        g_srcidx[g_rp[d.x] + atomicAdd(&g_cur[d.x], 1)] = s.x;
        g_srcidx[g_rp[d.y] + atomicAdd(&g_cur[d.y], 1)] = s.y;
        g_srcidx[g_rp[d.z] + atomicAdd(&g_cur[d.z], 1)] = s.z;
        g_srcidx[g_rp[d.w] + atomicAdd(&g_cur[d.w], 1)] = s.w;
    } else {
        for (int j = i4; j < e; j++) {
            int d = dst[j];
            g_srcidx[g_rp[d] + atomicAdd(&g_cur[d], 1)] = src[j];
        }
    }
}

__global__ void scatter_loops(int n) {
    int v = blockIdx.x * blockDim.x + threadIdx.x;
    if (v < n) g_srcidx[g_rp[v] + atomicAdd(&g_cur[v], 1)] = v;
}

// ================= tf32 tensor-core GEMM with fused alpha epilogue =================
// C_half[M,256] = A[M,256] @ B[256,256]  (tf32 mma, fp32 accumulate)
// asv/adv partials per column block (blockIdx.x in {0,1}), no atomics.
#define BMg 128
#define BNg 128
#define BKg 32
// dynamic smem layout (floats):
//  As: 2 buffers x 4096   (m in [0,128), k in [0,32), idx = m*32 + (k ^ ((m&7)<<2)))
//  Bs: 2 buffers x 4352   (k in [0,32), n in [0,128), idx = k*136 + n)
//  red: 1024              (row*8 + warp_n*2 + {0,1})
#define SM_AS_OFF 0
#define SM_BS_OFF 8192
#define SM_RED_OFF 16896
#define SM_FLOATS 17920

__device__ __forceinline__ void cpasync16(uint32_t dst, const void* src, bool ok) {
    int sz = ok ? 16 : 0;
    asm volatile("cp.async.cg.shared.global [%0], [%1], 16, %2;\n"
                 :: "r"(dst), "l"(src), "r"(sz));
}

__device__ __forceinline__ void mma_tf32(float* d, const unsigned* a, const unsigned* b) {
    asm volatile(
        "mma.sync.aligned.m16n8k8.row.col.f32.tf32.tf32.f32 "
        "{%0,%1,%2,%3}, {%4,%5,%6,%7}, {%8,%9}, {%0,%1,%2,%3};"
        : "+f"(d[0]), "+f"(d[1]), "+f"(d[2]), "+f"(d[3])
        : "r"(a[0]), "r"(a[1]), "r"(a[2]), "r"(a[3]), "r"(b[0]), "r"(b[1]));
}

__device__ __forceinline__ void load_tile_tc(const float* __restrict__ A,
                                             const float* __restrict__ B,
                                             int rowBase, int colBase, int kt, int buf,
                                             int tid, uint32_t sA, uint32_t sB, int M) {
#pragma unroll
    for (int i = 0; i < 4; i++) {
        int id = tid + 256 * i;
        int m = id >> 3;
        int kc4 = (id & 7) << 2;
        int gr = rowBase + m;
        bool ok = gr < M;
        const float* srcp = A + (size_t)(ok ? gr : 0) * DD + kt * BKg + kc4;
        uint32_t dst = sA + (uint32_t)((buf * 4096 + m * 32 + (kc4 ^ ((m & 7) << 2))) * 4);
        cpasync16(dst, srcp, ok);
    }
#pragma unroll
    for (int i = 0; i < 4; i++) {
        int id = tid + 256 * i;
        int r = id >> 5;
        int c4 = (id & 31) << 2;
        const float* srcp = B + (size_t)(kt * BKg + r) * DD + colBase + c4;
        uint32_t dst = sB + (uint32_t)((buf * 4352 + r * 136 + c4) * 4);
        cpasync16(dst, srcp, true);
    }
    asm volatile("cp.async.commit_group;");
}

__global__ __launch_bounds__(256, 2)
void sgemm_tc(const float* __restrict__ A, const float* __restrict__ B,
              __half* __restrict__ Ch,
              const float* __restrict__ a_src, const float* __restrict__ a_dst,
              float* __restrict__ asv, float* __restrict__ adv, int M) {
    extern __shared__ float sm[];
    float* red = sm + SM_RED_OFF;
    int tid = threadIdx.x;
    int lane = tid & 31;
    int warp = tid >> 5;
    int lq = lane & 3;        // thread-in-group
    int lr = lane >> 2;       // group id
    int warp_m = warp & 1;    // 2 warp rows
    int warp_n = warp >> 1;   // 4 warp cols
    int m0 = warp_m * 64;
    int n0 = warp_n * 32;
    int rowBase = blockIdx.y * BMg;
    int colBase = blockIdx.x * BNg;

    uint32_t sA = (uint32_t)__cvta_generic_to_shared(sm);
    uint32_t sB = sA + SM_BS_OFF * 4;

    float acc[16][4];
#pragma unroll
    for (int i = 0; i < 16; i++)
#pragma unroll
        for (int j = 0; j < 4; j++) acc[i][j] = 0.f;

    load_tile_tc(A, B, rowBase, colBase, 0, 0, tid, sA, sB, M);

    const int NTk = DD / BKg;  // 8
    for (int kt = 0; kt < NTk; kt++) {
        if (kt < NTk - 1) {
            load_tile_tc(A, B, rowBase, colBase, kt + 1, (kt + 1) & 1, tid, sA, sB, M);
            asm volatile("cp.async.wait_group 1;");
        } else {
            asm volatile("cp.async.wait_group 0;");
        }
        __syncthreads();

        int buf = kt & 1;
        const float* baseA = sm + buf * 4096;
        const float* baseB = sm + SM_BS_OFF + buf * 4352;
        int swA = lr << 2;  // (m&7)<<2 for both row halves (m0,tm*16 keep low3 = lr)

#pragma unroll
        for (int ks = 0; ks < 4; ks++) {
            int kk = ks * 8;
            unsigned aR[4][4], bR[4][2];
            int kA0 = (kk + lq) ^ swA;
            int kA1 = (kk + lq + 4) ^ swA;
#pragma unroll
            for (int tm = 0; tm < 4; tm++) {
                int mr = m0 + tm * 16 + lr;
                aR[tm][0] = __float_as_uint(baseA[mr * 32 + kA0]);
                aR[tm][1] = __float_as_uint(baseA[(mr + 8) * 32 + kA0]);
                aR[tm][2] = __float_as_uint(baseA[mr * 32 + kA1]);
                aR[tm][3] = __float_as_uint(baseA[(mr + 8) * 32 + kA1]);
            }
#pragma unroll
            for (int tn = 0; tn < 4; tn++) {
                int nc = n0 + tn * 8 + lr;
                bR[tn][0] = __float_as_uint(baseB[(kk + lq) * 136 + nc]);
                bR[tn][1] = __float_as_uint(baseB[(kk + lq + 4) * 136 + nc]);
            }
#pragma unroll
            for (int tm = 0; tm < 4; tm++)
#pragma unroll
                for (int tn = 0; tn < 4; tn++)
                    mma_tf32(acc[tm * 4 + tn], aR[tm], bR[tn]);
        }
        __syncthreads();
    }

    // ---- epilogue: fp16 C store + alpha partial dots ----
    float asx[8], adx[8];
#pragma unroll
    for (int tn = 0; tn < 4; tn++) {
#pragma unroll
        for (int j = 0; j < 2; j++) {
            int gc = colBase + n0 + tn * 8 + 2 * lq + j;
            asx[tn * 2 + j] = __ldg(a_src + gc);
            adx[tn * 2 + j] = __ldg(a_dst + gc);
        }
    }

#pragma unroll
    for (int tm = 0; tm < 4; tm++) {
        int gr0 = rowBase + m0 + tm * 16 + lr;
        int gr1 = gr0 + 8;
        // fp16 stores
#pragma unroll
        for (int tn = 0; tn < 4; tn++) {
            int gc = colBase + n0 + tn * 8 + 2 * lq;
            if (gr0 < M) {
                __half2 h = __floats2half2_rn(acc[tm * 4 + tn][0], acc[tm * 4 + tn][1]);
                *(__half2*)(Ch + (size_t)gr0 * DD + gc) = h;
            }
            if (gr1 < M) {
                __half2 h = __floats2half2_rn(acc[tm * 4 + tn][2], acc[tm * 4 + tn][3]);
                *(__half2*)(Ch + (size_t)gr1 * DD + gc) = h;
            }
        }
        // alpha partials per (row half)
#pragma unroll
        for (int half = 0; half < 2; half++) {
            float ps = 0.f, pd = 0.f;
#pragma unroll
            for (int tn = 0; tn < 4; tn++) {
                float c0 = acc[tm * 4 + tn][half * 2 + 0];
                float c1 = acc[tm * 4 + tn][half * 2 + 1];
                ps += c0 * asx[tn * 2] + c1 * asx[tn * 2 + 1];
                pd += c0 * adx[tn * 2] + c1 * adx[tn * 2 + 1];
            }
            // reduce across the 4 lanes of the quad (lq dimension)
#pragma unroll
            for (int off = 1; off < 4; off <<= 1) {
                ps += __shfl_xor_sync(0xffffffffu, ps, off);
                pd += __shfl_xor_sync(0xffffffffu, pd, off);
            }
            if (lq == 0) {
                int row = m0 + tm * 16 + half * 8 + lr;
                red[row * 8 + warp_n * 2 + 0] = ps;
                red[row * 8 + warp_n * 2 + 1] = pd;
            }
        }
    }
    __syncthreads();

    if (tid < 128) {
        int gr = rowBase + tid;
        if (gr < M) {
            float ps = red[tid * 8 + 0] + red[tid * 8 + 2] + red[tid * 8 + 4] + red[tid * 8 + 6];
            float pd = red[tid * 8 + 1] + red[tid * 8 + 3] + red[tid * 8 + 5] + red[tid * 8 + 7];
            asv[blockIdx.x * NN + gr] = ps;
            adv[blockIdx.x * NN + gr] = pd;
        }
    }
}

// ---------------- fused GAT aggregation (softmax + weighted sum + bias + leaky) ----
// one warp per destination node; h rows are fp16
__global__ __launch_bounds__(256)
void gat_aggregate(const __half* __restrict__ h,
                   const float* __restrict__ asv, const float* __restrict__ adv,
                   const float* __restrict__ bias, float* __restrict__ out, int n) {
    int warp = (blockIdx.x * blockDim.x + threadIdx.x) >> 5;
    int lane = threadIdx.x & 31;
    if (warp >= n) return;
    int v = warp;
    int beg = g_rp[v], end = g_rp[v + 1];
    float adval = adv[v] + adv[NN + v];

    float acc[8];
#pragma unroll
    for (int i = 0; i < 8; i++) acc[i] = 0.f;
    float ssum = 0.f;

    for (int j0 = beg; j0 < end; j0 += 32) {
        int j = j0 + lane;
        float w = 0.f; int s = 0;
        if (j < end) {
            s = g_srcidx[j];
            float e = leaky(asv[s] + asv[NN + s] + adval, 0.2f);
            w = __expf(e);   // logits bounded; no max-shift needed
        }
        ssum += w;
        int cnt = min(32, end - j0);
        int k = 0;
        for (; k + 2 <= cnt; k += 2) {
            float wk0 = __shfl_sync(0xffffffffu, w, k);
            float wk1 = __shfl_sync(0xffffffffu, w, k + 1);
            int sk0 = __shfl_sync(0xffffffffu, s, k);
            int sk1 = __shfl_sync(0xffffffffu, s, k + 1);
            uint4 ha = __ldg((const uint4*)(h + (size_t)sk0 * DD) + lane);
            uint4 hb = __ldg((const uint4*)(h + (size_t)sk1 * DD) + lane);
            const __half2* pa = (const __half2*)&ha;
            const __half2* pb = (const __half2*)&hb;
#pragma unroll
            for (int q = 0; q < 4; q++) {
                float2 fa = __half22float2(pa[q]);
                float2 fb = __half22float2(pb[q]);
                acc[2 * q + 0] += wk0 * fa.x + wk1 * fb.x;
                acc[2 * q + 1] += wk0 * fa.y + wk1 * fb.y;
            }
        }
        if (k < cnt) {
            float wk = __shfl_sync(0xffffffffu, w, k);
            int sk = __shfl_sync(0xffffffffu, s, k);
            uint4 ha = __ldg((const uint4*)(h + (size_t)sk * DD) + lane);
            const __half2* pa = (const __half2*)&ha;
#pragma unroll
            for (int q = 0; q < 4; q++) {
                float2 fa = __half22float2(pa[q]);
                acc[2 * q + 0] += wk * fa.x;
                acc[2 * q + 1] += wk * fa.y;
            }
        }
    }
#pragma unroll
    for (int off = 16; off; off >>= 1) ssum += __shfl_xor_sync(0xffffffffu, ssum, off);
    float inv = 1.0f / ssum;   // self loop guarantees ssum > 0

    float* op = out + (size_t)v * DD + lane * 8;
    float4 o0, o1;
    o0.x = leaky(acc[0] * inv + __ldg(bias + lane * 8 + 0), 0.01f);
    o0.y = leaky(acc[1] * inv + __ldg(bias + lane * 8 + 1), 0.01f);
    o0.z = leaky(acc[2] * inv + __ldg(bias + lane * 8 + 2), 0.01f);
    o0.w = leaky(acc[3] * inv + __ldg(bias + lane * 8 + 3), 0.01f);
    o1.x = leaky(acc[4] * inv + __ldg(bias + lane * 8 + 4), 0.01f);
    o1.y = leaky(acc[5] * inv + __ldg(bias + lane * 8 + 5), 0.01f);
    o1.z = leaky(acc[6] * inv + __ldg(bias + lane * 8 + 6), 0.01f);
    o1.w = leaky(acc[7] * inv + __ldg(bias + lane * 8 + 7), 0.01f);
    *(float4*)op       = o0;
    *(float4*)(op + 4) = o1;
}

// ---------------- pooling ----------------
#define NSPLIT 16
__global__ void pool_kernel(const float* __restrict__ t, const int* __restrict__ batch, int n) {
    int g = blockIdx.x;
    int split = blockIdx.y;
    int lo = lowerb(batch, n, g);
    int hi = lowerb(batch, n, g + 1);
    int cnt = hi - lo;
    if (cnt <= 0) return;
    int per = (cnt + NSPLIT - 1) / NSPLIT;
    int s0 = lo + split * per;
    int s1 = min(hi, s0 + per);
    if (s0 >= s1) return;
    int d = threadIdx.x;
    float a = 0.f;
    for (int nn = s0; nn < s1; nn++) a += t[(size_t)nn * DD + d];
    atomicAdd(&g_sums[g * DD + d], a);
}

// ---------------- finalize: mean + BN + linear ----------------
__global__ void finalize_kernel(const int* __restrict__ batch,
                                const float* __restrict__ gamma, const float* __restrict__ beta,
                                const float* __restrict__ mean, const float* __restrict__ var,
                                const float* __restrict__ Wl, const float* __restrict__ bl,
                                float* __restrict__ out, int n) {
    int g = blockIdx.x;
    int d = threadIdx.x;
    __shared__ float p[DD];
    __shared__ int scnt;
    if (d == 0) scnt = lowerb(batch, n, g + 1) - lowerb(batch, n, g);
    __syncthreads();
    float c = fmaxf((float)scnt, 1.0f);
    float vv = g_sums[g * DD + d] / c;
    vv = (vv - mean[d]) * rsqrtf(var[d] + 1e-5f) * gamma[d] + beta[d];
    p[d] = vv;
    __syncthreads();
    float o = bl[d];
    const float* wr = Wl + (size_t)d * DD;
    for (int k = 0; k < DD; k++) o += p[k] * wr[k];
    out[(size_t)g * DD + d] = o;
}

// ---------------- launch ----------------
extern "C" void kernel_launch(void* const* d_in, const int* in_sizes, int n_in,
                              void* d_out, int out_size) {
    const float* x      = (const float*)d_in[0];
    const int*   ei     = (const int*)d_in[1];
    const int*   batch  = (const int*)d_in[2];
    const float* W1     = (const float*)d_in[3];
    const float* a1s    = (const float*)d_in[4];
    const float* a1d    = (const float*)d_in[5];
    const float* b1     = (const float*)d_in[6];
    const float* W2     = (const float*)d_in[7];
    const float* a2s    = (const float*)d_in[8];
    const float* a2d    = (const float*)d_in[9];
    const float* b2     = (const float*)d_in[10];
    const float* gam    = (const float*)d_in[11];
    const float* bet    = (const float*)d_in[12];
    const float* mu     = (const float*)d_in[13];
    const float* var    = (const float*)d_in[14];
    const float* Wl     = (const float*)d_in[15];
    const float* bl     = (const float*)d_in[16];
    float* out = (float*)d_out;

    const int n = in_sizes[2];         // 20000
    const int e = in_sizes[1] / 2;     // 640000
    const int* srcp = ei;
    const int* dstp = ei + e;

    __half* hhp;  cudaGetSymbolAddress((void**)&hhp, g_hh);
    float* tptr;  cudaGetSymbolAddress((void**)&tptr, g_t);
    float* asp;   cudaGetSymbolAddress((void**)&asp, g_as);
    float* adp;   cudaGetSymbolAddress((void**)&adp, g_ad);

    const int T = 256;
    const int smemBytes = SM_FLOATS * 4;  // 71680
    static int attrSet = 0;
    if (!attrSet) {
        cudaFuncSetAttribute(sgemm_tc, cudaFuncAttributeMaxDynamicSharedMemorySize, smemBytes);
        attrSet = 1;
    }

    init_kernel<<<(NN + T - 1) / T, T>>>();

    // CSR build (once; reused by both layers)
    hist_kernel<<<((e + 3) / 4 + T - 1) / T, T>>>(dstp, e);
    scan_kernel<<<1, 1024>>>(n);
    scatter_edges<<<((e + 3) / 4 + T - 1) / T, T>>>(srcp, dstp, e);
    scatter_loops<<<(n + T - 1) / T, T>>>(n);

    dim3 ggrid(DD / BNg, (n + BMg - 1) / BMg);
    int aggBlocks = (n * 32 + T - 1) / T;

    // layer 1
    sgemm_tc<<<ggrid, 256, smemBytes>>>(x, W1, hhp, a1s, a1d, asp, adp, n);
    gat_aggregate<<<aggBlocks, T>>>(hhp, asp, adp, b1, tptr, n);

    // layer 2 (alpha buffers fully overwritten by GEMM2 — no zeroing needed)
    sgemm_tc<<<ggrid, 256, smemBytes>>>(tptr, W2, hhp, a2s, a2d, asp, adp, n);
    gat_aggregate<<<aggBlocks, T>>>(hhp, asp, adp, b2, tptr, n);

    // pool + finalize (BN folded onto pooled means — pooling is linear)
    dim3 pgrid(GG, NSPLIT);
    pool_kernel<<<pgrid, DD>>>(tptr, batch, n);
    finalize_kernel<<<GG, DD>>>(batch, gam, bet, mu, var, Wl, bl, out, n);
}

// round 5
// speedup vs baseline: 2.0857x; 1.0467x over previous
#include <cuda_runtime.h>
#include <cuda_fp16.h>
#include <cstdint>
#include <math.h>

// Problem constants (fixed by the reference)
#define NN 20000
#define DD 256
#define EE 640000
#define GG 64
#define ET (EE + NN)   // edges + self loops

// ---------------- device scratch (no allocations allowed) ----------------
__device__ __half g_hh[NN * DD];      // GEMM output in fp16 (gather payload)
__device__ float  g_t[NN * DD];       // aggregate output (fp32)
__device__ float  g_as[2 * NN];       // alpha_src partials (per column block)
__device__ float  g_ad[2 * NN];       // alpha_dst partials
__device__ int    g_cnt[NN];          // histogram
__device__ int    g_cur[NN];          // scatter cursor
__device__ int    g_rp[NN + 1];       // CSR row pointers (by dst)
__device__ int    g_srcidx[ET];       // src node ids grouped by dst
__device__ float  g_sums[GG * DD];    // pooled sums

// ---------------- helpers ----------------
__device__ __forceinline__ float leaky(float x, float s) { return x > 0.f ? x : s * x; }

__device__ int lowerb(const int* __restrict__ a, int n, int key) {
    int lo = 0, hi = n;
    while (lo < hi) { int mid = (lo + hi) >> 1; if (a[mid] < key) lo = mid + 1; else hi = mid; }
    return lo;
}

// round-to-nearest fp32 -> tf32 (unbiased; critical for accuracy)
__device__ __forceinline__ unsigned f2tf32(float f) {
    unsigned u;
    asm("cvt.rna.tf32.f32 %0, %1;" : "=r"(u) : "f"(f));
    return u;
}

// ---------------- init (zero cnt/cur/sums in one launch) ----------------
__global__ void init_kernel() {
    int i = blockIdx.x * blockDim.x + threadIdx.x;
    if (i < NN) { g_cnt[i] = 0; g_cur[i] = 0; }
    if (i < GG * DD) g_sums[i] = 0.f;
}

// ---------------- CSR build ----------------
__global__ void hist_kernel(const int* __restrict__ dst, int e) {
    int i = blockIdx.x * blockDim.x + threadIdx.x;
    int i4 = i * 4;
    if (i4 + 3 < e) {
        int4 d = *(const int4*)(dst + i4);
        atomicAdd(&g_cnt[d.x], 1);
        atomicAdd(&g_cnt[d.y], 1);
        atomicAdd(&g_cnt[d.z], 1);
        atomicAdd(&g_cnt[d.w], 1);
    } else {
        for (int j = i4; j < e; j++) atomicAdd(&g_cnt[dst[j]], 1);
    }
}

// exclusive scan of (g_cnt[i] + 1), single block, thread-sequential chunks
__global__ void scan_kernel(int n) {
    __shared__ int part[1024];
    int tid = threadIdx.x;
    const int C = (n + 1023) >> 10;     // 20 for n=20000
    int s0 = tid * C;
    int s1 = min(n, s0 + C);
    int local[32];
    int sum = 0;
    for (int i = s0; i < s1; i++) { local[i - s0] = sum; sum += g_cnt[i] + 1; }
    part[tid] = sum;
    __syncthreads();
    for (int off = 1; off < 1024; off <<= 1) {
        int t = (tid >= off) ? part[tid - off] : 0;
        __syncthreads();
        part[tid] += t;
        __syncthreads();
    }
    int base = (tid > 0) ? part[tid - 1] : 0;
    for (int i = s0; i < s1; i++) g_rp[i] = base + local[i - s0];
    if (tid == 1023) g_rp[n] = part[1023];
}

__global__ void scatter_edges(const int* __restrict__ src, const int* __restrict__ dst, int e) {
    int i = blockIdx.x * blockDim.x + threadIdx.x;
    int i4 = i * 4;
    if (i4 + 3 < e) {
        int4 s = *(const int4*)(src + i4);
        int4 d = *(const int4*)(dst + i4);
        g_srcidx[g_rp[d.x] + atomicAdd(&g_cur[d.x], 1)] = s.x;
        g_srcidx[g_rp[d.y] + atomicAdd(&g_cur[d.y], 1)] = s.y;
        g_srcidx[g_rp[d.z] + atomicAdd(&g_cur[d.z], 1)] = s.z;
        g_srcidx[g_rp[d.w] + atomicAdd(&g_cur[d.w], 1)] = s.w;
    } else {
        for (int j = i4; j < e; j++) {
            int d = dst[j];
            g_srcidx[g_rp[d] + atomicAdd(&g_cur[d], 1)] = src[j];
        }
    }
}

// self-loop goes to the LAST slot of each row deterministically (edges fill
// rp[v]..rp[v]+cnt-1, row has cnt+1 slots) — no atomic needed
__global__ void scatter_loops(int n) {
    int v = blockIdx.x * blockDim.x + threadIdx.x;
    if (v < n) g_srcidx[g_rp[v + 1] - 1] = v;
}

// ================= tf32 tensor-core GEMM with fused alpha epilogue =================
// C_half[M,256] = A[M,256] @ B[256,256]  (tf32 mma RN-converted, fp32 accumulate)
// asv/adv partials per column block (blockIdx.x in {0,1}), no atomics.
#define BMg 128
#define BNg 128
#define BKg 32
// dynamic smem layout (floats):
//  As: 2 buffers x 4096   (m in [0,128), k in [0,32), idx = m*32 + (k ^ ((m&7)<<2)))
//  Bs: 2 buffers x 4352   (k in [0,32), n in [0,128), idx = k*136 + n)
//  red: 1024              (row*8 + warp_n*2 + {0,1})
#define SM_AS_OFF 0
#define SM_BS_OFF 8192
#define SM_RED_OFF 16896
#define SM_FLOATS 17920

__device__ __forceinline__ void cpasync16(uint32_t dst, const void* src, bool ok) {
    int sz = ok ? 16 : 0;
    asm volatile("cp.async.cg.shared.global [%0], [%1], 16, %2;\n"
                 :: "r"(dst), "l"(src), "r"(sz));
}

__device__ __forceinline__ void mma_tf32(float* d, const unsigned* a, const unsigned* b) {
    asm volatile(
        "mma.sync.aligned.m16n8k8.row.col.f32.tf32.tf32.f32 "
        "{%0,%1,%2,%3}, {%4,%5,%6,%7}, {%8,%9}, {%0,%1,%2,%3};"
        : "+f"(d[0]), "+f"(d[1]), "+f"(d[2]), "+f"(d[3])
        : "r"(a[0]), "r"(a[1]), "r"(a[2]), "r"(a[3]), "r"(b[0]), "r"(b[1]));
}

__device__ __forceinline__ void load_tile_tc(const float* __restrict__ A,
                                             const float* __restrict__ B,
                                             int rowBase, int colBase, int kt, int buf,
                                             int tid, uint32_t sA, uint32_t sB, int M) {
#pragma unroll
    for (int i = 0; i < 4; i++) {
        int id = tid + 256 * i;
        int m = id >> 3;
        int kc4 = (id & 7) << 2;
        int gr = rowBase + m;
        bool ok = gr < M;
        const float* srcp = A + (size_t)(ok ? gr : 0) * DD + kt * BKg + kc4;
        uint32_t dst = sA + (uint32_t)((buf * 4096 + m * 32 + (kc4 ^ ((m & 7) << 2))) * 4);
        cpasync16(dst, srcp, ok);
    }
#pragma unroll
    for (int i = 0; i < 4; i++) {
        int id = tid + 256 * i;
        int r = id >> 5;
        int c4 = (id & 31) << 2;
        const float* srcp = B + (size_t)(kt * BKg + r) * DD + colBase + c4;
        uint32_t dst = sB + (uint32_t)((buf * 4352 + r * 136 + c4) * 4);
        cpasync16(dst, srcp, true);
    }
    asm volatile("cp.async.commit_group;");
}

__global__ __launch_bounds__(256, 2)
void sgemm_tc(const float* __restrict__ A, const float* __restrict__ B,
              __half* __restrict__ Ch,
              const float* __restrict__ a_src, const float* __restrict__ a_dst,
              float* __restrict__ asv, float* __restrict__ adv, int M) {
    extern __shared__ float sm[];
    float* red = sm + SM_RED_OFF;
    int tid = threadIdx.x;
    int lane = tid & 31;
    int warp = tid >> 5;
    int lq = lane & 3;        // thread-in-group
    int lr = lane >> 2;       // group id
    int warp_m = warp & 1;    // 2 warp rows
    int warp_n = warp >> 1;   // 4 warp cols
    int m0 = warp_m * 64;
    int n0 = warp_n * 32;
    int rowBase = blockIdx.y * BMg;
    int colBase = blockIdx.x * BNg;

    uint32_t sA = (uint32_t)__cvta_generic_to_shared(sm);
    uint32_t sB = sA + SM_BS_OFF * 4;

    float acc[16][4];
#pragma unroll
    for (int i = 0; i < 16; i++)
#pragma unroll
        for (int j = 0; j < 4; j++) acc[i][j] = 0.f;

    load_tile_tc(A, B, rowBase, colBase, 0, 0, tid, sA, sB, M);

    const int NTk = DD / BKg;  // 8
    for (int kt = 0; kt < NTk; kt++) {
        if (kt < NTk - 1) {
            load_tile_tc(A, B, rowBase, colBase, kt + 1, (kt + 1) & 1, tid, sA, sB, M);
            asm volatile("cp.async.wait_group 1;");
        } else {
            asm volatile("cp.async.wait_group 0;");
        }
        __syncthreads();

        int buf = kt & 1;
        const float* baseA = sm + buf * 4096;
        const float* baseB = sm + SM_BS_OFF + buf * 4352;
        int swA = lr << 2;  // (m&7)<<2 for both row halves (m0,tm*16 keep low3 = lr)

#pragma unroll
        for (int ks = 0; ks < 4; ks++) {
            int kk = ks * 8;
            unsigned aR[4][4], bR[4][2];
            int kA0 = (kk + lq) ^ swA;
            int kA1 = (kk + lq + 4) ^ swA;
#pragma unroll
            for (int tm = 0; tm < 4; tm++) {
                int mr = m0 + tm * 16 + lr;
                aR[tm][0] = f2tf32(baseA[mr * 32 + kA0]);
                aR[tm][1] = f2tf32(baseA[(mr + 8) * 32 + kA0]);
                aR[tm][2] = f2tf32(baseA[mr * 32 + kA1]);
                aR[tm][3] = f2tf32(baseA[(mr + 8) * 32 + kA1]);
            }
#pragma unroll
            for (int tn = 0; tn < 4; tn++) {
                int nc = n0 + tn * 8 + lr;
                bR[tn][0] = f2tf32(baseB[(kk + lq) * 136 + nc]);
                bR[tn][1] = f2tf32(baseB[(kk + lq + 4) * 136 + nc]);
            }
#pragma unroll
            for (int tm = 0; tm < 4; tm++)
#pragma unroll
                for (int tn = 0; tn < 4; tn++)
                    mma_tf32(acc[tm * 4 + tn], aR[tm], bR[tn]);
        }
        __syncthreads();
    }

    // ---- epilogue: fp16 C store + alpha partial dots ----
    float asx[8], adx[8];
#pragma unroll
    for (int tn = 0; tn < 4; tn++) {
#pragma unroll
        for (int j = 0; j < 2; j++) {
            int gc = colBase + n0 + tn * 8 + 2 * lq + j;
            asx[tn * 2 + j] = __ldg(a_src + gc);
            adx[tn * 2 + j] = __ldg(a_dst + gc);
        }
    }

#pragma unroll
    for (int tm = 0; tm < 4; tm++) {
        int gr0 = rowBase + m0 + tm * 16 + lr;
        int gr1 = gr0 + 8;
        // fp16 stores
#pragma unroll
        for (int tn = 0; tn < 4; tn++) {
            int gc = colBase + n0 + tn * 8 + 2 * lq;
            if (gr0 < M) {
                __half2 h = __floats2half2_rn(acc[tm * 4 + tn][0], acc[tm * 4 + tn][1]);
                *(__half2*)(Ch + (size_t)gr0 * DD + gc) = h;
            }
            if (gr1 < M) {
                __half2 h = __floats2half2_rn(acc[tm * 4 + tn][2], acc[tm * 4 + tn][3]);
                *(__half2*)(Ch + (size_t)gr1 * DD + gc) = h;
            }
        }
        // alpha partials per (row half)
#pragma unroll
        for (int half = 0; half < 2; half++) {
            float ps = 0.f, pd = 0.f;
#pragma unroll
            for (int tn = 0; tn < 4; tn++) {
                float c0 = acc[tm * 4 + tn][half * 2 + 0];
                float c1 = acc[tm * 4 + tn][half * 2 + 1];
                ps += c0 * asx[tn * 2] + c1 * asx[tn * 2 + 1];
                pd += c0 * adx[tn * 2] + c1 * adx[tn * 2 + 1];
            }
            // reduce across the 4 lanes of the quad (lq dimension)
#pragma unroll
            for (int off = 1; off < 4; off <<= 1) {
                ps += __shfl_xor_sync(0xffffffffu, ps, off);
                pd += __shfl_xor_sync(0xffffffffu, pd, off);
            }
            if (lq == 0) {
                int row = m0 + tm * 16 + half * 8 + lr;
                red[row * 8 + warp_n * 2 + 0] = ps;
                red[row * 8 + warp_n * 2 + 1] = pd;
            }
        }
    }
    __syncthreads();

    if (tid < 128) {
        int gr = rowBase + tid;
        if (gr < M) {
            float ps = red[tid * 8 + 0] + red[tid * 8 + 2] + red[tid * 8 + 4] + red[tid * 8 + 6];
            float pd = red[tid * 8 + 1] + red[tid * 8 + 3] + red[tid * 8 + 5] + red[tid * 8 + 7];
            asv[blockIdx.x * NN + gr] = ps;
            adv[blockIdx.x * NN + gr] = pd;
        }
    }
}

// ---------------- fused GAT aggregation (softmax + weighted sum + bias + leaky) ----
// one warp per destination node; h rows are fp16
__global__ __launch_bounds__(256)
void gat_aggregate(const __half* __restrict__ h,
                   const float* __restrict__ asv, const float* __restrict__ adv,
                   const float* __restrict__ bias, float* __restrict__ out, int n) {
    int warp = (blockIdx.x * blockDim.x + threadIdx.x) >> 5;
    int lane = threadIdx.x & 31;
    if (warp >= n) return;
    int v = warp;
    int beg = g_rp[v], end = g_rp[v + 1];
    float adval = adv[v] + adv[NN + v];

    float acc[8];
#pragma unroll
    for (int i = 0; i < 8; i++) acc[i] = 0.f;
    float ssum = 0.f;

    for (int j0 = beg; j0 < end; j0 += 32) {
        int j = j0 + lane;
        float w = 0.f; int s = 0;
        if (j < end) {
            s = g_srcidx[j];
            float e = leaky(asv[s] + asv[NN + s] + adval, 0.2f);
            w = __expf(e);   // logits bounded; no max-shift needed
        }
        ssum += w;
        int cnt = min(32, end - j0);
        int k = 0;
        for (; k + 2 <= cnt; k += 2) {
            float wk0 = __shfl_sync(0xffffffffu, w, k);
            float wk1 = __shfl_sync(0xffffffffu, w, k + 1);
            int sk0 = __shfl_sync(0xffffffffu, s, k);
            int sk1 = __shfl_sync(0xffffffffu, s, k + 1);
            uint4 ha = __ldg((const uint4*)(h + (size_t)sk0 * DD) + lane);
            uint4 hb = __ldg((const uint4*)(h + (size_t)sk1 * DD) + lane);
            const __half2* pa = (const __half2*)&ha;
            const __half2* pb = (const __half2*)&hb;
#pragma unroll
            for (int q = 0; q < 4; q++) {
                float2 fa = __half22float2(pa[q]);
                float2 fb = __half22float2(pb[q]);
                acc[2 * q + 0] += wk0 * fa.x + wk1 * fb.x;
                acc[2 * q + 1] += wk0 * fa.y + wk1 * fb.y;
            }
        }
        if (k < cnt) {
            float wk = __shfl_sync(0xffffffffu, w, k);
            int sk = __shfl_sync(0xffffffffu, s, k);
            uint4 ha = __ldg((const uint4*)(h + (size_t)sk * DD) + lane);
            const __half2* pa = (const __half2*)&ha;
#pragma unroll
            for (int q = 0; q < 4; q++) {
                float2 fa = __half22float2(pa[q]);
                acc[2 * q + 0] += wk * fa.x;
                acc[2 * q + 1] += wk * fa.y;
            }
        }
    }
#pragma unroll
    for (int off = 16; off; off >>= 1) ssum += __shfl_xor_sync(0xffffffffu, ssum, off);
    float inv = 1.0f / ssum;   // self loop guarantees ssum > 0

    float* op = out + (size_t)v * DD + lane * 8;
    float4 o0, o1;
    o0.x = leaky(acc[0] * inv + __ldg(bias + lane * 8 + 0), 0.01f);
    o0.y = leaky(acc[1] * inv + __ldg(bias + lane * 8 + 1), 0.01f);
    o0.z = leaky(acc[2] * inv + __ldg(bias + lane * 8 + 2), 0.01f);
    o0.w = leaky(acc[3] * inv + __ldg(bias + lane * 8 + 3), 0.01f);
    o1.x = leaky(acc[4] * inv + __ldg(bias + lane * 8 + 4), 0.01f);
    o1.y = leaky(acc[5] * inv + __ldg(bias + lane * 8 + 5), 0.01f);
    o1.z = leaky(acc[6] * inv + __ldg(bias + lane * 8 + 6), 0.01f);
    o1.w = leaky(acc[7] * inv + __ldg(bias + lane * 8 + 7), 0.01f);
    *(float4*)op       = o0;
    *(float4*)(op + 4) = o1;
}

// ---------------- pooling ----------------
#define NSPLIT 16
__global__ void pool_kernel(const float* __restrict__ t, const int* __restrict__ batch, int n) {
    int g = blockIdx.x;
    int split = blockIdx.y;
    int lo = lowerb(batch, n, g);
    int hi = lowerb(batch, n, g + 1);
    int cnt = hi - lo;
    if (cnt <= 0) return;
    int per = (cnt + NSPLIT - 1) / NSPLIT;
    int s0 = lo + split * per;
    int s1 = min(hi, s0 + per);
    if (s0 >= s1) return;
    int d = threadIdx.x;
    float a = 0.f;
    for (int nn = s0; nn < s1; nn++) a += t[(size_t)nn * DD + d];
    atomicAdd(&g_sums[g * DD + d], a);
}

// ---------------- finalize: mean + BN + linear ----------------
__global__ void finalize_kernel(const int* __restrict__ batch,
                                const float* __restrict__ gamma, const float* __restrict__ beta,
                                const float* __restrict__ mean, const float* __restrict__ var,
                                const float* __restrict__ Wl, const float* __restrict__ bl,
                                float* __restrict__ out, int n) {
    int g = blockIdx.x;
    int d = threadIdx.x;
    __shared__ float p[DD];
    __shared__ int scnt;
    if (d == 0) scnt = lowerb(batch, n, g + 1) - lowerb(batch, n, g);
    __syncthreads();
    float c = fmaxf((float)scnt, 1.0f);
    float vv = g_sums[g * DD + d] / c;
    vv = (vv - mean[d]) * rsqrtf(var[d] + 1e-5f) * gamma[d] + beta[d];
    p[d] = vv;
    __syncthreads();
    float o = bl[d];
    const float* wr = Wl + (size_t)d * DD;
    for (int k = 0; k < DD; k++) o += p[k] * wr[k];
    out[(size_t)g * DD + d] = o;
}

// ---------------- launch ----------------
extern "C" void kernel_launch(void* const* d_in, const int* in_sizes, int n_in,
                              void* d_out, int out_size) {
    const float* x      = (const float*)d_in[0];
    const int*   ei     = (const int*)d_in[1];
    const int*   batch  = (const int*)d_in[2];
    const float* W1     = (const float*)d_in[3];
    const float* a1s    = (const float*)d_in[4];
    const float* a1d    = (const float*)d_in[5];
    const float* b1     = (const float*)d_in[6];
    const float* W2     = (const float*)d_in[7];
    const float* a2s    = (const float*)d_in[8];
    const float* a2d    = (const float*)d_in[9];
    const float* b2     = (const float*)d_in[10];
    const float* gam    = (const float*)d_in[11];
    const float* bet    = (const float*)d_in[12];
    const float* mu     = (const float*)d_in[13];
    const float* var    = (const float*)d_in[14];
    const float* Wl     = (const float*)d_in[15];
    const float* bl     = (const float*)d_in[16];
    float* out = (float*)d_out;

    const int n = in_sizes[2];         // 20000
    const int e = in_sizes[1] / 2;     // 640000
    const int* srcp = ei;
    const int* dstp = ei + e;

    __half* hhp;  cudaGetSymbolAddress((void**)&hhp, g_hh);
    float* tptr;  cudaGetSymbolAddress((void**)&tptr, g_t);
    float* asp;   cudaGetSymbolAddress((void**)&asp, g_as);
    float* adp;   cudaGetSymbolAddress((void**)&adp, g_ad);

    const int T = 256;
    const int smemBytes = SM_FLOATS * 4;  // 71680

    static cudaStream_t s2 = nullptr;
    static cudaEvent_t evFork = nullptr, evJoin = nullptr;
    static int attrSet = 0;
    if (!attrSet) {
        cudaFuncSetAttribute(sgemm_tc, cudaFuncAttributeMaxDynamicSharedMemorySize, smemBytes);
        cudaStreamCreateWithFlags(&s2, cudaStreamNonBlocking);
        cudaEventCreateWithFlags(&evFork, cudaEventDisableTiming);
        cudaEventCreateWithFlags(&evJoin, cudaEventDisableTiming);
        attrSet = 1;
    }

    init_kernel<<<(NN + T - 1) / T, T>>>();

    // fork: CSR build on s2, concurrent with GEMM1 on the main stream
    cudaEventRecord(evFork, 0);
    cudaStreamWaitEvent(s2, evFork, 0);
    hist_kernel<<<((e + 3) / 4 + T - 1) / T, T, 0, s2>>>(dstp, e);
    scan_kernel<<<1, 1024, 0, s2>>>(n);
    scatter_edges<<<((e + 3) / 4 + T - 1) / T, T, 0, s2>>>(srcp, dstp, e);
    scatter_loops<<<(n + T - 1) / T, T, 0, s2>>>(n);
    cudaEventRecord(evJoin, s2);

    dim3 ggrid(DD / BNg, (n + BMg - 1) / BMg);
    int aggBlocks = (n * 32 + T - 1) / T;

    // layer 1 GEMM overlaps the CSR build
    sgemm_tc<<<ggrid, 256, smemBytes>>>(x, W1, hhp, a1s, a1d, asp, adp, n);

    // join: aggregation needs the CSR
    cudaStreamWaitEvent(0, evJoin, 0);
    gat_aggregate<<<aggBlocks, T>>>(hhp, asp, adp, b1, tptr, n);

    // layer 2 (alpha buffers fully overwritten by GEMM2 — no zeroing needed)
    sgemm_tc<<<ggrid, 256, smemBytes>>>(tptr, W2, hhp, a2s, a2d, asp, adp, n);
    gat_aggregate<<<aggBlocks, T>>>(hhp, asp, adp, b2, tptr, n);

    // pool + finalize (BN folded onto pooled means — pooling is linear)
    dim3 pgrid(GG, NSPLIT);
    pool_kernel<<<pgrid, DD>>>(tptr, batch, n);
    finalize_kernel<<<GG, DD>>>(batch, gam, bet, mu, var, Wl, bl, out, n);
}